// round 15
// baseline (speedup 1.0000x reference)
#include <cuda_runtime.h>
#include <cstdint>
#include <math_constants.h>

#define D        64
#define KC       512
#define NCHUNK   64
#define MT       128
#define TILES    2048
#define NROWS    262144
#define TPB      256
#define GRID     148
#define XSTRIDE  68

#define MARG_COEF 1.9531e-4f
#define MARG_ABS  4.0e-4f

#define OFF_X     0
#define OFF_EH    (MT * XSTRIDE)
#define OFF_NRM   (OFF_EH + 32768)
#define OFF_RSQ   (OFF_NRM + KC)
#define OFF_MARG  (OFF_RSQ + MT)
#define OFF_BK    (OFF_MARG + MT)
#define OFF_LCNT  (OFF_BK + MT)
#define OFF_LIST  (OFF_LCNT + 1)
#define OFF_WSUM  (OFF_LIST + MT)
#define SM_FLOATS (OFF_WSUM + 8)
#define SM_BYTES  (SM_FLOATS * 4)

__device__ float        g_cta[GRID];
__device__ unsigned int g_done = 0;

__device__ __forceinline__ float to_tf32(float v) {
    uint32_t u;
    asm("cvt.rn.tf32.f32 %0, %1;" : "=r"(u) : "f"(v));
    return __uint_as_float(u);
}

__device__ __forceinline__ void mma_tf32(float& c0, float& c1, float& c2, float& c3,
                                         float a0, float a1, float a2, float a3,
                                         float b0, float b1) {
    asm volatile(
        "mma.sync.aligned.m16n8k8.row.col.f32.tf32.tf32.f32 "
        "{%0,%1,%2,%3}, {%4,%5,%6,%7}, {%8,%9}, {%0,%1,%2,%3};"
        : "+f"(c0), "+f"(c1), "+f"(c2), "+f"(c3)
        : "r"(__float_as_uint(a0)), "r"(__float_as_uint(a1)),
          "r"(__float_as_uint(a2)), "r"(__float_as_uint(a3)),
          "r"(__float_as_uint(b0)), "r"(__float_as_uint(b1)));
}

// branchless top-2 update on SCALARS only (R14 used arrays -> local-mem spill)
#define T2_UPD(s, k, b1, k1, b2) \
    do { float _s = (s); \
        float _t = fmaxf(_s, b1); \
        b2 = fminf(b2, _t); \
        bool _c = _s < b1; \
        k1 = _c ? (k) : k1; \
        b1 = _c ? _s : b1; \
    } while (0)

#define T2_MRG(v1, i1, v2, w1, j1, w2) \
    do { \
        float _mx = fmaxf(v1, w1); \
        v2 = fminf(fminf(v2, w2), _mx); \
        bool _c = (w1 < v1) || (w1 == v1 && (j1) < i1); \
        i1 = _c ? (j1) : i1; \
        v1 = fminf(v1, w1); \
    } while (0)

// one j-slot: 8 MMAs over s2 into scalar accums, then 4 score updates
#define CHUNK_BODY(J, CA0, CA1, CA2, CA3, B1A, K1A, B2A, B1B, K1B, B2B) \
    do { \
        float CA0 = 0.f, CA1 = 0.f, CA2 = 0.f, CA3 = 0.f; \
        _Pragma("unroll") \
        for (int s2 = 0; s2 < 4; s2++) { \
            float4 Bv = EH4[((n4 * 4 + (J)) * 4 + s2) * 32 + lane]; \
            mma_tf32(CA0, CA1, CA2, CA3, \
                     Ah[8*s2], Ah[8*s2+1], Ah[8*s2+2], Ah[8*s2+3], Bv.x, Bv.y); \
            mma_tf32(CA0, CA1, CA2, CA3, \
                     Ah[8*s2+4], Ah[8*s2+5], Ah[8*s2+6], Ah[8*s2+7], Bv.z, Bv.w); \
        } \
        const int n_ = n4 * 4 + (J); \
        const float2 nv = *(const float2*)&sm[OFF_NRM + n_ * 8 + 2 * tig]; \
        const int k0_ = n_ * 8 + 2 * tig; \
        float s00 = (rs0 + nv.x) - 2.0f * CA0; \
        float s01 = (rs0 + nv.y) - 2.0f * CA1; \
        float s10 = (rs1 + nv.x) - 2.0f * CA2; \
        float s11 = (rs1 + nv.y) - 2.0f * CA3; \
        T2_UPD(s00, k0_,     B1A, K1A, B2A); \
        T2_UPD(s01, k0_ + 1, B1A, K1A, B2A); \
        T2_UPD(s10, k0_,     B1B, K1B, B2B); \
        T2_UPD(s11, k0_ + 1, B1B, K1B, B2B); \
    } while (0)

__global__ void __launch_bounds__(TPB, 1)
vq_main(const float* __restrict__ x, const float* __restrict__ emb,
        float* __restrict__ out, int out_size) {
    extern __shared__ float sm[];
    const int tid  = threadIdx.x;
    const int wid  = tid >> 5;
    const int lane = tid & 31;
    const int g    = lane >> 2;
    const int tig  = lane & 3;

    float4* EH4   = (float4*)&sm[OFF_EH];
    int*    sBk   = (int*)&sm[OFF_BK];
    int*    sLCnt = (int*)&sm[OFF_LCNT];
    int*    sList = (int*)&sm[OFF_LIST];

    // ---- one-time: E hh frag pack + code norms ----
    for (int slot = tid; slot < NCHUNK * 4 * 32; slot += TPB) {
        const int n  = slot >> 7;
        const int s2 = (slot >> 5) & 3;
        const int l  = slot & 31;
        const int lg = l >> 2, lt = l & 3;
        const float* er = emb + (size_t)(n * 8 + lg) * D;
        const int c0 = 16 * s2 + lt;
        EH4[slot] = make_float4(to_tf32(er[c0]), to_tf32(er[c0 + 4]),
                                to_tf32(er[c0 + 8]), to_tf32(er[c0 + 12]));
    }
    for (int k = tid; k < KC; k += TPB) {
        const float* er = emb + (size_t)k * D;
        float s = 0.f;
        #pragma unroll
        for (int d = 0; d < D; d++) s += er[d] * er[d];
        sm[OFF_NRM + k] = s;
    }
    __syncthreads();

    float ctaAcc = 0.f;

    for (int t = blockIdx.x; t < TILES; t += GRID) {
        const float4* xb = (const float4*)(x + (size_t)t * (MT * D));

        #pragma unroll
        for (int it = 0; it < 8; it++) {
            const int i = it * TPB + tid;
            float4 v = xb[i];
            const int r = i >> 4, c4 = i & 15;
            *(float4*)&sm[OFF_X + r * XSTRIDE + c4 * 4] = v;
        }
        if (tid == 0) *sLCnt = 0;
        __syncthreads();

        if (tid < MT) {
            const int r = tid;
            float rowsq = 0.f, sabs = 0.f;
            #pragma unroll
            for (int i = 0; i < 16; i++) {
                const int c4 = (i + r) & 15;
                float4 v = *(const float4*)&sm[OFF_X + r * XSTRIDE + c4 * 4];
                rowsq += ((v.x * v.x + v.y * v.y) + v.z * v.z) + v.w * v.w;
                sabs  += fabsf(v.x) + fabsf(v.y) + fabsf(v.z) + fabsf(v.w);
            }
            sm[OFF_RSQ + r]  = rowsq;
            sm[OFF_MARG + r] = MARG_COEF * sabs + MARG_ABS;
        }
        __syncthreads();

        // ---- hh MMA pass: each warp 16 rows x 512 codes; ALL state scalar ----
        {
            const int wb = wid * 16;
            const int r0 = wb + g, r1 = wb + 8 + g;

            float Ah[32];
            #pragma unroll
            for (int s = 0; s < 8; s++) {
                const int c = 8 * s + tig;
                Ah[4*s+0] = to_tf32(sm[OFF_X + r0 * XSTRIDE + c]);
                Ah[4*s+1] = to_tf32(sm[OFF_X + r1 * XSTRIDE + c]);
                Ah[4*s+2] = to_tf32(sm[OFF_X + r0 * XSTRIDE + c + 4]);
                Ah[4*s+3] = to_tf32(sm[OFF_X + r1 * XSTRIDE + c + 4]);
            }
            const float rs0 = sm[OFF_RSQ + r0];
            const float rs1 = sm[OFF_RSQ + r1];

            // scalar trackers: 4 j-slots x 2 rows
            float b1a0 = CUDART_INF_F, b2a0 = CUDART_INF_F;
            float b1a1 = CUDART_INF_F, b2a1 = CUDART_INF_F;
            float b1a2 = CUDART_INF_F, b2a2 = CUDART_INF_F;
            float b1a3 = CUDART_INF_F, b2a3 = CUDART_INF_F;
            float b1b0 = CUDART_INF_F, b2b0 = CUDART_INF_F;
            float b1b1 = CUDART_INF_F, b2b1 = CUDART_INF_F;
            float b1b2 = CUDART_INF_F, b2b2 = CUDART_INF_F;
            float b1b3 = CUDART_INF_F, b2b3 = CUDART_INF_F;
            int k1a0 = 0, k1a1 = 0, k1a2 = 0, k1a3 = 0;
            int k1b0 = 0, k1b1 = 0, k1b2 = 0, k1b3 = 0;

            #pragma unroll 1
            for (int n4 = 0; n4 < NCHUNK / 4; n4++) {
                CHUNK_BODY(0, c00, c01, c02, c03, b1a0, k1a0, b2a0, b1b0, k1b0, b2b0);
                CHUNK_BODY(1, c10, c11, c12, c13, b1a1, k1a1, b2a1, b1b1, k1b1, b2b1);
                CHUNK_BODY(2, c20, c21, c22, c23, b1a2, k1a2, b2a2, b1b2, k1b2, b2b2);
                CHUNK_BODY(3, c30, c31, c32, c33, b1a3, k1a3, b2a3, b1b3, k1b3, b2b3);
            }

            // merge j-slots (ascending k order; tie -> lower k in macro)
            T2_MRG(b1a0, k1a0, b2a0, b1a1, k1a1, b2a1);
            T2_MRG(b1a0, k1a0, b2a0, b1a2, k1a2, b2a2);
            T2_MRG(b1a0, k1a0, b2a0, b1a3, k1a3, b2a3);
            T2_MRG(b1b0, k1b0, b2b0, b1b1, k1b1, b2b1);
            T2_MRG(b1b0, k1b0, b2b0, b1b2, k1b2, b2b2);
            T2_MRG(b1b0, k1b0, b2b0, b1b3, k1b3, b2b3);

            // merge across the 4 tig lanes
            #pragma unroll
            for (int off = 1; off <= 2; off <<= 1) {
                float w1 = __shfl_xor_sync(0xffffffffu, b1a0, off);
                float w2 = __shfl_xor_sync(0xffffffffu, b2a0, off);
                int   j1 = __shfl_xor_sync(0xffffffffu, k1a0, off);
                T2_MRG(b1a0, k1a0, b2a0, w1, j1, w2);
                w1 = __shfl_xor_sync(0xffffffffu, b1b0, off);
                w2 = __shfl_xor_sync(0xffffffffu, b2b0, off);
                j1 = __shfl_xor_sync(0xffffffffu, k1b0, off);
                T2_MRG(b1b0, k1b0, b2b0, w1, j1, w2);
            }

            if (tig == 0) {
                sBk[r0] = k1a0;
                if (!(b2a0 - b1a0 > sm[OFF_MARG + r0]))
                    sList[atomicAdd(sLCnt, 1)] = r0;
                sBk[r1] = k1b0;
                if (!(b2b0 - b1b0 > sm[OFF_MARG + r1]))
                    sList[atomicAdd(sLCnt, 1)] = r1;
            }
        }
        __syncthreads();

        // ---- full fp32 rescan for uncertified rows: one warp per row ----
        {
            const int L = *sLCnt;
            for (int i = wid; i < L; i += 8) {
                const int r = sList[i];
                float bb = CUDART_INF_F; int bk = 0;
                const float rsq = sm[OFF_RSQ + r];
                for (int c = 0; c < 16; c++) {
                    const int k = lane + 32 * c;
                    const float4* e4 = (const float4*)(emb + (size_t)k * D);
                    float dot = 0.f;
                    #pragma unroll
                    for (int q = 0; q < 16; q++) {
                        float4 ev = e4[q];
                        float4 xv = *(const float4*)&sm[OFF_X + r * XSTRIDE + q * 4];
                        dot += ev.x * xv.x + ev.y * xv.y + ev.z * xv.z + ev.w * xv.w;
                    }
                    float s = (rsq + sm[OFF_NRM + k]) - 2.0f * dot;
                    if (s < bb || (s == bb && k < bk)) { bb = s; bk = k; }
                }
                #pragma unroll
                for (int off = 16; off > 0; off >>= 1) {
                    float ov = __shfl_xor_sync(0xffffffffu, bb, off);
                    int   ok = __shfl_xor_sync(0xffffffffu, bk, off);
                    if (ov < bb || (ov == bb && ok < bk)) { bb = ov; bk = ok; }
                }
                if (lane == 0) sBk[r] = bk;
            }
        }
        __syncthreads();

        // ---- gather + write quantized rows ----
        {
            float4* o4 = (float4*)(out + (size_t)t * (MT * D));
            const float4* e4 = (const float4*)emb;
            #pragma unroll
            for (int i4 = tid; i4 < MT * D / 4; i4 += TPB) {
                const int r = i4 >> 4, dd = i4 & 15;
                o4[i4] = e4[(size_t)sBk[r] * 16 + dd];
            }
        }
        // ---- exact per-row diffsq for losses ----
        if (tid < MT) {
            const int r = tid;
            const float* er = emb + (size_t)sBk[r] * D;
            float acc = 0.f;
            #pragma unroll 4
            for (int j = 0; j < D; j++) {
                const int idx = ((r << 2) + j) & 63;
                float d = sm[OFF_X + r * XSTRIDE + idx] - er[idx];
                acc += d * d;
            }
            #pragma unroll
            for (int off = 16; off > 0; off >>= 1)
                acc += __shfl_down_sync(0xffffffffu, acc, off);
            if ((tid & 31) == 0) sm[OFF_WSUM + (tid >> 5)] = acc;
        }
        __syncthreads();
        if (tid == 0)
            ctaAcc += ((sm[OFF_WSUM] + sm[OFF_WSUM+1]) + sm[OFF_WSUM+2]) + sm[OFF_WSUM+3];
        __syncthreads();
    }

    // ---- fused finalize ----
    if (tid == 0) {
        g_cta[blockIdx.x] = ctaAcc;
        __threadfence();
        unsigned int prev = atomicAdd(&g_done, 1);
        if (prev == GRID - 1) {
            float s = 0.f;
            for (int i = 0; i < GRID; i++) s += g_cta[i];
            float mean = s / (float)((long long)NROWS * D);
            out[out_size - 2] = mean;          // codebook_loss
            out[out_size - 1] = 0.25f * mean;  // commitment_loss (BETA)
            g_done = 0;
        }
    }
}

extern "C" void kernel_launch(void* const* d_in, const int* in_sizes, int n_in,
                              void* d_out, int out_size) {
    const float* x   = (const float*)d_in[0];
    const float* emb = (const float*)d_in[1];
    float* out = (float*)d_out;

    cudaFuncSetAttribute(vq_main, cudaFuncAttributeMaxDynamicSharedMemorySize,
                         SM_BYTES);
    vq_main<<<GRID, TPB, SM_BYTES>>>(x, emb, out, out_size);
}

// round 17
// speedup vs baseline: 2.6080x; 2.6080x over previous
#include <cuda_runtime.h>
#include <cstdint>
#include <math_constants.h>

#define D        64
#define KC       512
#define NCHUNK   64
#define MT       128
#define TILES    2048
#define NROWS    262144
#define TPB      256
#define GRID     148
#define XSTRIDE  68

#define MARG_COEF 1.9531e-4f
#define MARG_ABS  4.0e-4f

#define OFF_X     0
#define OFF_EH    (MT * XSTRIDE)
#define OFF_NRM   (OFF_EH + 32768)
#define OFF_RSQ   (OFF_NRM + KC)
#define OFF_MARG  (OFF_RSQ + MT)
#define OFF_BK    (OFF_MARG + MT)
#define OFF_LCNT  (OFF_BK + MT)
#define OFF_LIST  (OFF_LCNT + 1)
#define OFF_WSUM  (OFF_LIST + MT)
#define OFF_RSCS  (OFF_WSUM + 8)            // rescan scores: 128 rows x 8 warps
#define OFF_RSCK  (OFF_RSCS + MT * 8)       // rescan ks
#define SM_FLOATS (OFF_RSCK + MT * 8)
#define SM_BYTES  (SM_FLOATS * 4)           // ~178 KB

__device__ float        g_cta[GRID];
__device__ unsigned int g_done = 0;

__device__ __forceinline__ float to_tf32(float v) {
    uint32_t u;
    asm("cvt.rn.tf32.f32 %0, %1;" : "=r"(u) : "f"(v));
    return __uint_as_float(u);
}

__device__ __forceinline__ void mma_tf32(float& c0, float& c1, float& c2, float& c3,
                                         float a0, float a1, float a2, float a3,
                                         float b0, float b1) {
    asm volatile(
        "mma.sync.aligned.m16n8k8.row.col.f32.tf32.tf32.f32 "
        "{%0,%1,%2,%3}, {%4,%5,%6,%7}, {%8,%9}, {%0,%1,%2,%3};"
        : "+f"(c0), "+f"(c1), "+f"(c2), "+f"(c3)
        : "r"(__float_as_uint(a0)), "r"(__float_as_uint(a1)),
          "r"(__float_as_uint(a2)), "r"(__float_as_uint(a3)),
          "r"(__float_as_uint(b0)), "r"(__float_as_uint(b1)));
}

// branchless top-2 update (measured cheap in R15: alu 6.3%)
#define T2_UPD(s, k, b1, k1, b2) \
    do { float _s = (s); \
        float _t = fmaxf(_s, b1); \
        b2 = fminf(b2, _t); \
        bool _c = _s < b1; \
        k1 = _c ? (k) : k1; \
        b1 = _c ? _s : b1; \
    } while (0)

#define T2_MRG(v1, i1, v2, w1, j1, w2) \
    do { \
        float _mx = fmaxf(v1, w1); \
        v2 = fminf(fminf(v2, w2), _mx); \
        bool _c = (w1 < v1) || (w1 == v1 && (j1) < i1); \
        i1 = _c ? (j1) : i1; \
        v1 = fminf(v1, w1); \
    } while (0)

#define CHUNK_BODY(J, CA0, CA1, CA2, CA3, B1A, K1A, B2A, B1B, K1B, B2B) \
    do { \
        float CA0 = 0.f, CA1 = 0.f, CA2 = 0.f, CA3 = 0.f; \
        _Pragma("unroll") \
        for (int s2 = 0; s2 < 4; s2++) { \
            float4 Bv = EH4[((n4 * 4 + (J)) * 4 + s2) * 32 + lane]; \
            mma_tf32(CA0, CA1, CA2, CA3, \
                     Ah[8*s2], Ah[8*s2+1], Ah[8*s2+2], Ah[8*s2+3], Bv.x, Bv.y); \
            mma_tf32(CA0, CA1, CA2, CA3, \
                     Ah[8*s2+4], Ah[8*s2+5], Ah[8*s2+6], Ah[8*s2+7], Bv.z, Bv.w); \
        } \
        const int n_ = n4 * 4 + (J); \
        const float2 nv = *(const float2*)&sm[OFF_NRM + n_ * 8 + 2 * tig]; \
        const int k0_ = n_ * 8 + 2 * tig; \
        float s00 = (rs0 + nv.x) - 2.0f * CA0; \
        float s01 = (rs0 + nv.y) - 2.0f * CA1; \
        float s10 = (rs1 + nv.x) - 2.0f * CA2; \
        float s11 = (rs1 + nv.y) - 2.0f * CA3; \
        T2_UPD(s00, k0_,     B1A, K1A, B2A); \
        T2_UPD(s01, k0_ + 1, B1A, K1A, B2A); \
        T2_UPD(s10, k0_,     B1B, K1B, B2B); \
        T2_UPD(s11, k0_ + 1, B1B, K1B, B2B); \
    } while (0)

__global__ void __launch_bounds__(TPB, 1)
vq_main(const float* __restrict__ x, const float* __restrict__ emb,
        float* __restrict__ out, int out_size) {
    extern __shared__ float sm[];
    const int tid  = threadIdx.x;
    const int wid  = tid >> 5;
    const int lane = tid & 31;
    const int g    = lane >> 2;
    const int tig  = lane & 3;

    float4* EH4   = (float4*)&sm[OFF_EH];
    int*    sBk   = (int*)&sm[OFF_BK];
    int*    sLCnt = (int*)&sm[OFF_LCNT];
    int*    sList = (int*)&sm[OFF_LIST];
    float*  sRscS = &sm[OFF_RSCS];
    int*    sRscK = (int*)&sm[OFF_RSCK];

    // ---- one-time: E hh frag pack + code norms ----
    for (int slot = tid; slot < NCHUNK * 4 * 32; slot += TPB) {
        const int n  = slot >> 7;
        const int s2 = (slot >> 5) & 3;
        const int l  = slot & 31;
        const int lg = l >> 2, lt = l & 3;
        const float* er = emb + (size_t)(n * 8 + lg) * D;
        const int c0 = 16 * s2 + lt;
        EH4[slot] = make_float4(to_tf32(er[c0]), to_tf32(er[c0 + 4]),
                                to_tf32(er[c0 + 8]), to_tf32(er[c0 + 12]));
    }
    for (int k = tid; k < KC; k += TPB) {
        const float* er = emb + (size_t)k * D;
        float s = 0.f;
        #pragma unroll
        for (int d = 0; d < D; d++) s += er[d] * er[d];
        sm[OFF_NRM + k] = s;
    }
    __syncthreads();

    // per-lane rescan slice: 2 codes, cached in registers ONCE (reused all tiles)
    const int kRa = 64 * wid + lane;
    const int kRb = kRa + 32;
    float4 Ea[16], Eb[16];
    #pragma unroll
    for (int q = 0; q < 16; q++) {
        Ea[q] = ((const float4*)(emb + (size_t)kRa * D))[q];
        Eb[q] = ((const float4*)(emb + (size_t)kRb * D))[q];
    }
    const float nRa = sm[OFF_NRM + kRa];
    const float nRb = sm[OFF_NRM + kRb];

    float ctaAcc = 0.f;

    for (int t = blockIdx.x; t < TILES; t += GRID) {
        const float4* xb = (const float4*)(x + (size_t)t * (MT * D));

        #pragma unroll
        for (int it = 0; it < 8; it++) {
            const int i = it * TPB + tid;
            float4 v = xb[i];
            const int r = i >> 4, c4 = i & 15;
            *(float4*)&sm[OFF_X + r * XSTRIDE + c4 * 4] = v;
        }
        if (tid == 0) *sLCnt = 0;
        __syncthreads();

        if (tid < MT) {
            const int r = tid;
            float rowsq = 0.f, sabs = 0.f;
            #pragma unroll
            for (int i = 0; i < 16; i++) {
                const int c4 = (i + r) & 15;
                float4 v = *(const float4*)&sm[OFF_X + r * XSTRIDE + c4 * 4];
                rowsq += ((v.x * v.x + v.y * v.y) + v.z * v.z) + v.w * v.w;
                sabs  += fabsf(v.x) + fabsf(v.y) + fabsf(v.z) + fabsf(v.w);
            }
            sm[OFF_RSQ + r]  = rowsq;
            sm[OFF_MARG + r] = MARG_COEF * sabs + MARG_ABS;
        }
        __syncthreads();

        // ---- hh MMA pass: each warp 16 rows x 512 codes ----
        {
            const int wb = wid * 16;
            const int r0 = wb + g, r1 = wb + 8 + g;

            float Ah[32];
            #pragma unroll
            for (int s = 0; s < 8; s++) {
                const int c = 8 * s + tig;
                Ah[4*s+0] = to_tf32(sm[OFF_X + r0 * XSTRIDE + c]);
                Ah[4*s+1] = to_tf32(sm[OFF_X + r1 * XSTRIDE + c]);
                Ah[4*s+2] = to_tf32(sm[OFF_X + r0 * XSTRIDE + c + 4]);
                Ah[4*s+3] = to_tf32(sm[OFF_X + r1 * XSTRIDE + c + 4]);
            }
            const float rs0 = sm[OFF_RSQ + r0];
            const float rs1 = sm[OFF_RSQ + r1];

            float b1a0 = CUDART_INF_F, b2a0 = CUDART_INF_F;
            float b1a1 = CUDART_INF_F, b2a1 = CUDART_INF_F;
            float b1a2 = CUDART_INF_F, b2a2 = CUDART_INF_F;
            float b1a3 = CUDART_INF_F, b2a3 = CUDART_INF_F;
            float b1b0 = CUDART_INF_F, b2b0 = CUDART_INF_F;
            float b1b1 = CUDART_INF_F, b2b1 = CUDART_INF_F;
            float b1b2 = CUDART_INF_F, b2b2 = CUDART_INF_F;
            float b1b3 = CUDART_INF_F, b2b3 = CUDART_INF_F;
            int k1a0 = 0, k1a1 = 0, k1a2 = 0, k1a3 = 0;
            int k1b0 = 0, k1b1 = 0, k1b2 = 0, k1b3 = 0;

            #pragma unroll 1
            for (int n4 = 0; n4 < NCHUNK / 4; n4++) {
                CHUNK_BODY(0, c00, c01, c02, c03, b1a0, k1a0, b2a0, b1b0, k1b0, b2b0);
                CHUNK_BODY(1, c10, c11, c12, c13, b1a1, k1a1, b2a1, b1b1, k1b1, b2b1);
                CHUNK_BODY(2, c20, c21, c22, c23, b1a2, k1a2, b2a2, b1b2, k1b2, b2b2);
                CHUNK_BODY(3, c30, c31, c32, c33, b1a3, k1a3, b2a3, b1b3, k1b3, b2b3);
            }

            T2_MRG(b1a0, k1a0, b2a0, b1a1, k1a1, b2a1);
            T2_MRG(b1a0, k1a0, b2a0, b1a2, k1a2, b2a2);
            T2_MRG(b1a0, k1a0, b2a0, b1a3, k1a3, b2a3);
            T2_MRG(b1b0, k1b0, b2b0, b1b1, k1b1, b2b1);
            T2_MRG(b1b0, k1b0, b2b0, b1b2, k1b2, b2b2);
            T2_MRG(b1b0, k1b0, b2b0, b1b3, k1b3, b2b3);

            #pragma unroll
            for (int off = 1; off <= 2; off <<= 1) {
                float w1 = __shfl_xor_sync(0xffffffffu, b1a0, off);
                float w2 = __shfl_xor_sync(0xffffffffu, b2a0, off);
                int   j1 = __shfl_xor_sync(0xffffffffu, k1a0, off);
                T2_MRG(b1a0, k1a0, b2a0, w1, j1, w2);
                w1 = __shfl_xor_sync(0xffffffffu, b1b0, off);
                w2 = __shfl_xor_sync(0xffffffffu, b2b0, off);
                j1 = __shfl_xor_sync(0xffffffffu, k1b0, off);
                T2_MRG(b1b0, k1b0, b2b0, w1, j1, w2);
            }

            if (tig == 0) {
                sBk[r0] = k1a0;
                if (!(b2a0 - b1a0 > sm[OFF_MARG + r0]))
                    sList[atomicAdd(sLCnt, 1)] = r0;
                sBk[r1] = k1b0;
                if (!(b2b0 - b1b0 > sm[OFF_MARG + r1]))
                    sList[atomicAdd(sLCnt, 1)] = r1;
            }
        }
        __syncthreads();

        // ---- cooperative fp32 rescan: all warps per row, reg-cached emb ----
        {
            const int L = *sLCnt;
            for (int i = 0; i < L; i++) {
                const int r = sList[i];
                const float rsq = sm[OFF_RSQ + r];
                float da = 0.f, db = 0.f;
                #pragma unroll
                for (int q = 0; q < 16; q++) {
                    float4 xv = *(const float4*)&sm[OFF_X + r * XSTRIDE + q * 4];
                    da += xv.x * Ea[q].x + xv.y * Ea[q].y
                        + xv.z * Ea[q].z + xv.w * Ea[q].w;
                    db += xv.x * Eb[q].x + xv.y * Eb[q].y
                        + xv.z * Eb[q].z + xv.w * Eb[q].w;
                }
                float sa = (rsq + nRa) - 2.0f * da;
                float sb = (rsq + nRb) - 2.0f * db;
                float bs = sa; int bk = kRa;
                if (sb < bs) { bs = sb; bk = kRb; }     // kRa < kRb: tie keeps lower
                #pragma unroll
                for (int off = 16; off > 0; off >>= 1) {
                    float ov = __shfl_xor_sync(0xffffffffu, bs, off);
                    int   ok = __shfl_xor_sync(0xffffffffu, bk, off);
                    if (ov < bs || (ov == bs && ok < bk)) { bs = ov; bk = ok; }
                }
                if (lane == 0) { sRscS[i * 8 + wid] = bs; sRscK[i * 8 + wid] = bk; }
            }
            __syncthreads();
            // final merge: ascending warp = ascending k; strict < keeps lowest k
            if (tid < L) {
                const int r = sList[tid];
                float bs = CUDART_INF_F; int bk = 0;
                #pragma unroll
                for (int w = 0; w < 8; w++) {
                    float s = sRscS[tid * 8 + w];
                    int   k = sRscK[tid * 8 + w];
                    if (s < bs || (s == bs && k < bk)) { bs = s; bk = k; }
                }
                sBk[r] = bk;
            }
        }
        __syncthreads();

        // ---- gather + write quantized rows ----
        {
            float4* o4 = (float4*)(out + (size_t)t * (MT * D));
            const float4* e4 = (const float4*)emb;
            #pragma unroll
            for (int i4 = tid; i4 < MT * D / 4; i4 += TPB) {
                const int r = i4 >> 4, dd = i4 & 15;
                o4[i4] = e4[(size_t)sBk[r] * 16 + dd];
            }
        }
        // ---- exact per-row diffsq for losses ----
        if (tid < MT) {
            const int r = tid;
            const float* er = emb + (size_t)sBk[r] * D;
            float acc = 0.f;
            #pragma unroll 4
            for (int j = 0; j < D; j++) {
                const int idx = ((r << 2) + j) & 63;
                float d = sm[OFF_X + r * XSTRIDE + idx] - er[idx];
                acc += d * d;
            }
            #pragma unroll
            for (int off = 16; off > 0; off >>= 1)
                acc += __shfl_down_sync(0xffffffffu, acc, off);
            if ((tid & 31) == 0) sm[OFF_WSUM + (tid >> 5)] = acc;
        }
        __syncthreads();
        if (tid == 0)
            ctaAcc += ((sm[OFF_WSUM] + sm[OFF_WSUM+1]) + sm[OFF_WSUM+2]) + sm[OFF_WSUM+3];
        __syncthreads();
    }

    // ---- fused finalize ----
    if (tid == 0) {
        g_cta[blockIdx.x] = ctaAcc;
        __threadfence();
        unsigned int prev = atomicAdd(&g_done, 1);
        if (prev == GRID - 1) {
            float s = 0.f;
            for (int i = 0; i < GRID; i++) s += g_cta[i];
            float mean = s / (float)((long long)NROWS * D);
            out[out_size - 2] = mean;          // codebook_loss
            out[out_size - 1] = 0.25f * mean;  // commitment_loss (BETA)
            g_done = 0;
        }
    }
}

extern "C" void kernel_launch(void* const* d_in, const int* in_sizes, int n_in,
                              void* d_out, int out_size) {
    const float* x   = (const float*)d_in[0];
    const float* emb = (const float*)d_in[1];
    float* out = (float*)d_out;

    cudaFuncSetAttribute(vq_main, cudaFuncAttributeMaxDynamicSharedMemorySize,
                         SM_BYTES);
    vq_main<<<GRID, TPB, SM_BYTES>>>(x, emb, out, out_size);
}